// round 15
// baseline (speedup 1.0000x reference)
#include <cuda_runtime.h>
#include <math.h>
#include <stdint.h>

// HashGrid2D, Morton(512)+grid bucketed sort, fused gather:
//   hist(ILP4, saves rank) -> scan -> scatter(ILP4, atomic-free)
//   -> fused gather: warp = level x 32 sorted points, 256 pts/block,
//      2-iteration software pipeline (launch_bounds 512,2 -> 64 regs),
//      predicated XOR-pair ulonglong2 loads, packed f32x2 lerp blend,
//      conflict-free transpose, __stcs writeback, hist re-zero fused.

#define N_LEVELS 16
#define TBITS    19
#define TSIZE    (1u << TBITS)
#define HMASK    (TSIZE - 1u)
#define PRIME_Y  2654435761u

#define MAXN     1048576
#define KEYBITS  19
#define NBINS    (1 << KEYBITS)
#define NCHUNK   (NBINS / 1024)

#define PPB      256
#define GITER    8

struct ScaleArr { float s[N_LEVELS]; };

__device__ int    d_hist[NBINS];
__device__ int    d_counter;
__device__ int    d_rank[MAXN];
__device__ float4 d_pts[MAXN];

// -------- packed f32x2 helpers (sm_100+) --------
__device__ __forceinline__ unsigned long long f2_sub(unsigned long long a, unsigned long long b) {
    unsigned long long r;
    asm("sub.rn.f32x2 %0, %1, %2;" : "=l"(r) : "l"(a), "l"(b));
    return r;
}
__device__ __forceinline__ unsigned long long f2_fma(unsigned long long a, unsigned long long b, unsigned long long c) {
    unsigned long long r;
    asm("fma.rn.f32x2 %0, %1, %2, %3;" : "=l"(r) : "l"(a), "l"(b), "l"(c));
    return r;
}
__device__ __forceinline__ unsigned long long f2_bcast(float v) {
    unsigned long long r;
    asm("mov.b64 %0, {%1, %1};" : "=l"(r) : "f"(v));
    return r;
}

// -------- morton --------
__device__ __forceinline__ unsigned part1by1(unsigned v) {
    v &= 0xffffu;
    v = (v | (v << 8)) & 0x00FF00FFu;
    v = (v | (v << 4)) & 0x0F0F0F0Fu;
    v = (v | (v << 2)) & 0x33333333u;
    v = (v | (v << 1)) & 0x55555555u;
    return v;
}
__device__ __forceinline__ unsigned key19(float xf, float yf, int g) {
    unsigned mx = (unsigned)(xf * 512.0f); if (mx > 511u) mx = 511u;
    unsigned my = (unsigned)(yf * 512.0f); if (my > 511u) my = 511u;
    return (part1by1(mx) | (part1by1(my) << 1)) | ((unsigned)g << 18);
}

__global__ void zero_kernel() {
    int t = blockIdx.x * blockDim.x + threadIdx.x;
    if (t < NBINS / 4) ((int4*)d_hist)[t] = make_int4(0, 0, 0, 0);
    if (t == 0) d_counter = 0;
}

// -------- pass 1: histogram + rank capture --------
__global__ void __launch_bounds__(128) hist_kernel(
    const float2* __restrict__ x, const int* __restrict__ gidx, int N) {
    int t  = blockIdx.x * blockDim.x + threadIdx.x;
    int p0 = t * 4;
    if (p0 >= N) return;
    if (p0 + 3 < N) {
        const float4* x4 = (const float4*)x;
        float4 a = __ldg(&x4[t * 2]);
        float4 b = __ldg(&x4[t * 2 + 1]);
        int4   g = __ldg(&((const int4*)gidx)[t]);
        float xs[4] = {a.x, a.z, b.x, b.z};
        float ys[4] = {a.y, a.w, b.y, b.w};
        int   gs[4] = {g.x, g.y, g.z, g.w};
        int r[4];
        #pragma unroll
        for (int k = 0; k < 4; k++)
            r[k] = atomicAdd(&d_hist[key19(xs[k], ys[k], gs[k])], 1);
        ((int4*)(d_rank + p0))[0] = make_int4(r[0], r[1], r[2], r[3]);
    } else {
        for (int k = 0; k < 4 && p0 + k < N; k++) {
            float2 xy = __ldg(&x[p0 + k]);
            d_rank[p0 + k] =
                atomicAdd(&d_hist[key19(xy.x, xy.y, __ldg(&gidx[p0 + k]))], 1);
        }
    }
}

// -------- pass 2: per-chunk scan + atomic global base --------
__global__ void __launch_bounds__(1024) scan_kernel() {
    __shared__ int warpsum[32];
    __shared__ int sbase;
    const int tid  = threadIdx.x;
    const int lane = tid & 31;
    const int wid  = tid >> 5;
    const int idx  = blockIdx.x * 1024 + tid;

    const int v = d_hist[idx];
    int incl = v;
    #pragma unroll
    for (int d = 1; d < 32; d <<= 1) {
        int u = __shfl_up_sync(0xffffffffu, incl, d);
        if (lane >= d) incl += u;
    }
    if (lane == 31) warpsum[wid] = incl;
    __syncthreads();
    if (wid == 0) {
        int s = warpsum[lane];
        #pragma unroll
        for (int d = 1; d < 32; d <<= 1) {
            int u = __shfl_up_sync(0xffffffffu, s, d);
            if (lane >= d) s += u;
        }
        warpsum[lane] = s;
    }
    __syncthreads();
    const int inclT = incl + (wid ? warpsum[wid - 1] : 0);
    if (tid == 1023) sbase = atomicAdd(&d_counter, inclT);
    __syncthreads();
    d_hist[idx] = sbase + inclT - v;
}

// -------- pass 3: atomic-free scatter --------
__global__ void __launch_bounds__(128) scatter_kernel(
    const float2* __restrict__ x, const int* __restrict__ gidx, int N) {
    int t  = blockIdx.x * blockDim.x + threadIdx.x;
    int p0 = t * 4;
    if (p0 >= N) return;
    if (p0 + 3 < N) {
        const float4* x4 = (const float4*)x;
        float4 xa = __ldg(&x4[t * 2]);
        float4 xb = __ldg(&x4[t * 2 + 1]);
        int4   g  = __ldg(&((const int4*)gidx)[t]);
        int4   r  = ((const int4*)(d_rank + p0))[0];
        float xs[4] = {xa.x, xa.z, xb.x, xb.z};
        float ys[4] = {xa.y, xa.w, xb.y, xb.w};
        int   gs[4] = {g.x, g.y, g.z, g.w};
        int   rs[4] = {r.x, r.y, r.z, r.w};
        int base[4];
        #pragma unroll
        for (int k = 0; k < 4; k++)
            base[k] = __ldg(&d_hist[key19(xs[k], ys[k], gs[k])]);
        #pragma unroll
        for (int k = 0; k < 4; k++)
            d_pts[base[k] + rs[k]] = make_float4(xs[k], ys[k],
                                                 __int_as_float(gs[k]),
                                                 __int_as_float(p0 + k));
    } else {
        for (int k = 0; k < 4 && p0 + k < N; k++) {
            float2 xy = __ldg(&x[p0 + k]);
            int    g  = __ldg(&gidx[p0 + k]);
            int pos = __ldg(&d_hist[key19(xy.x, xy.y, g)]) + d_rank[p0 + k];
            d_pts[pos] = make_float4(xy.x, xy.y,
                                     __int_as_float(g),
                                     __int_as_float(p0 + k));
        }
    }
}

// -------- gather helper: one point's hash/addr state --------
struct GItem {
    unsigned h00, h10, h01, h11;
    unsigned ix;
    float wx, wy;
    const ulonglong2* baseu;
};

__device__ __forceinline__ GItem g_prep(float4 pt, float s,
                                        const ulonglong2* warpbase) {
    GItem r;
    const unsigned gbit = __float_as_uint(pt.z) & 1u;
    const float px = pt.x * s;
    const float py = pt.y * s;
    const int ixi = __float2int_rd(px);
    const int iyi = __float2int_rd(py);
    r.wx = px - (float)ixi;
    r.wy = py - (float)iyi;
    r.ix = (unsigned)ixi;
    const unsigned iy = (unsigned)iyi;
    r.baseu = warpbase + ((size_t)gbit << 22);   // 2^23 float2 = 2^22 u2
    const unsigned hy0 = iy * PRIME_Y;
    const unsigned hy1 = hy0 + PRIME_Y;
    r.h00 = ( r.ix       ^ hy0) & HMASK;
    r.h10 = ((r.ix + 1u) ^ hy0) & HMASK;
    r.h01 = ( r.ix       ^ hy1) & HMASK;
    r.h11 = ((r.ix + 1u) ^ hy1) & HMASK;
    return r;
}

__device__ __forceinline__ float2 g_blend(const GItem& it,
                                          ulonglong2 qa, ulonglong2 qb,
                                          ulonglong2 qc, ulonglong2 qd) {
    const unsigned long long u00 = (it.h00 & 1u) ? qa.y : qa.x;
    const unsigned long long u10 = (it.h10 & 1u) ? qb.y : qb.x;
    const unsigned long long u01 = (it.h01 & 1u) ? qc.y : qc.x;
    const unsigned long long u11 = (it.h11 & 1u) ? qd.y : qd.x;
    const unsigned long long wx2 = f2_bcast(it.wx);
    const unsigned long long wy2 = f2_bcast(it.wy);
    const unsigned long long fx0 = f2_fma(wx2, f2_sub(u10, u00), u00);
    const unsigned long long fx1 = f2_fma(wx2, f2_sub(u11, u01), u01);
    const unsigned long long o   = f2_fma(wy2, f2_sub(fx1, fx0), fx0);
    float2 of;
    asm("mov.b64 {%0, %1}, %2;" : "=f"(of.x), "=f"(of.y) : "l"(o));
    return of;
}

// -------- pass 4: fused gather, 2-deep software pipeline --------
__global__ void __launch_bounds__(512, 2) fused_gather_kernel(
    const float2* __restrict__ feat, float2* __restrict__ out2,
    int N, ScaleArr sc)
{
    __shared__ float4 spts[PPB];
    __shared__ float2 smres[N_LEVELS][PPB + 1];   // stride 257: conflict-free

    if (blockIdx.x < 256) {
        const int z = blockIdx.x * 512 + threadIdx.x;
        ((int4*)d_hist)[z] = make_int4(0, 0, 0, 0);
        if (z == 0) d_counter = 0;
    }

    const int i0   = blockIdx.x * PPB;
    const int warp = threadIdx.x >> 5;       // level
    const int lane = threadIdx.x & 31;

    #pragma unroll
    for (int k = 0; k < PPB / 512 + 1; k++) {
        const int j = threadIdx.x + k * 512;
        if (j < PPB) {
            const int i = i0 + j;
            spts[j] = (i < N) ? d_pts[i] : make_float4(0.f, 0.f, 0.f, 0.f);
        }
    }
    __syncthreads();

    const float s = sc.s[warp];
    const ulonglong2* __restrict__ warpbase =
        (const ulonglong2*)(feat + ((size_t)warp << TBITS));

    #pragma unroll
    for (int itp = 0; itp < GITER / 2; itp++) {
        const GItem A = g_prep(spts[(2 * itp)     * 32 + lane], s, warpbase);
        const GItem B = g_prep(spts[(2 * itp + 1) * 32 + lane], s, warpbase);

        // issue both iterations' loads before consuming either
        const ulonglong2 qaA = __ldg(A.baseu + (A.h00 >> 1));
        const ulonglong2 qcA = __ldg(A.baseu + (A.h01 >> 1));
        const ulonglong2 qaB = __ldg(B.baseu + (B.h00 >> 1));
        const ulonglong2 qcB = __ldg(B.baseu + (B.h01 >> 1));
        ulonglong2 qbA = qaA, qdA = qcA;
        if (A.ix & 1u) {
            qbA = __ldg(A.baseu + (A.h10 >> 1));
            qdA = __ldg(A.baseu + (A.h11 >> 1));
        }
        ulonglong2 qbB = qaB, qdB = qcB;
        if (B.ix & 1u) {
            qbB = __ldg(B.baseu + (B.h10 >> 1));
            qdB = __ldg(B.baseu + (B.h11 >> 1));
        }

        smres[warp][(2 * itp)     * 32 + lane] = g_blend(A, qaA, qbA, qcA, qdA);
        smres[warp][(2 * itp + 1) * 32 + lane] = g_blend(B, qaB, qbB, qcB, qdB);
    }
    __syncthreads();

    // writeback: level-major lanes; 16 consecutive threads = one point's line
    #pragma unroll
    for (int r = 0; r < PPB * N_LEVELS / 512; r++) {
        const int idx = threadIdx.x + r * 512;
        const int p = idx >> 4;
        const int l = idx & 15;
        if (i0 + p < N) {
            const int p_orig = __float_as_int(spts[p].w);
            __stcs(&out2[(size_t)p_orig * N_LEVELS + l], smres[l][p]);
        }
    }
}

// -------- fallback (N > MAXN): flat paired kernel --------
__global__ void __launch_bounds__(256) hashgrid2d_paired_kernel(
    const float2* __restrict__ x, const float2* __restrict__ feat,
    const int* __restrict__ gidx, float2* __restrict__ out,
    int n_total, ScaleArr sc)
{
    int t = blockIdx.x * blockDim.x + threadIdx.x;
    if (t >= n_total) return;
    int level = t & 15, p = t >> 4;
    float2 xy = __ldg(&x[p]);
    int g = __ldg(&gidx[p]);
    float s = sc.s[level];
    float px = xy.x * s, py = xy.y * s;
    int ixi = __float2int_rd(px), iyi = __float2int_rd(py);
    float wx = px - (float)ixi, wy = py - (float)iyi;
    unsigned ix = (unsigned)ixi, iy = (unsigned)iyi;
    const float4* base4 = (const float4*)(feat + ((size_t)(g * N_LEVELS + level) << TBITS));
    unsigned hy0 = iy * PRIME_Y, hy1 = hy0 + PRIME_Y;
    unsigned h00 = (ix ^ hy0) & HMASK, h01 = (ix ^ hy1) & HMASK;
    unsigned h10 = ((ix + 1u) ^ hy0) & HMASK;
    unsigned h11 = ((ix + 1u) ^ hy1) & HMASK;
    float4 qa = __ldg(base4 + (h00 >> 1));
    float4 qc = __ldg(base4 + (h01 >> 1));
    float4 qb = qa, qd = qc;
    if (ix & 1u) {
        qb = __ldg(base4 + (h10 >> 1));
        qd = __ldg(base4 + (h11 >> 1));
    }
    float2 f00 = (h00 & 1u) ? make_float2(qa.z, qa.w) : make_float2(qa.x, qa.y);
    float2 f10 = (h10 & 1u) ? make_float2(qb.z, qb.w) : make_float2(qb.x, qb.y);
    float2 f01 = (h01 & 1u) ? make_float2(qc.z, qc.w) : make_float2(qc.x, qc.y);
    float2 f11 = (h11 & 1u) ? make_float2(qd.z, qd.w) : make_float2(qd.x, qd.y);
    float w00 = (1.0f - wx) * (1.0f - wy), w10 = wx * (1.0f - wy);
    float w01 = (1.0f - wx) * wy,          w11 = wx * wy;
    float2 o;
    o.x = w00 * f00.x + w10 * f10.x + w01 * f01.x + w11 * f11.x;
    o.y = w00 * f00.y + w10 * f10.y + w01 * f01.y + w11 * f11.y;
    out[t] = o;
}

extern "C" void kernel_launch(void* const* d_in, const int* in_sizes, int n_in,
                              void* d_out, int out_size)
{
    const float2* x    = (const float2*)d_in[0];
    const float2* feat = (const float2*)d_in[1];
    const int*    gidx = (const int*)d_in[2];

    int N = in_sizes[0] / 2;

    ScaleArr sc;
    double bw = exp((log(512.0) - log(16.0)) / (double)(N_LEVELS - 1));
    for (int i = 0; i < N_LEVELS; i++) {
        int res = (int)(16.0 * pow(bw, (double)i));
        sc.s[i] = (float)(res - 1);
    }

    if (N > MAXN) {
        int n_total = N * N_LEVELS;
        hashgrid2d_paired_kernel<<<(n_total + 255) / 256, 256>>>(
            x, feat, gidx, (float2*)d_out, n_total, sc);
        return;
    }

    int gblocks = (N + PPB - 1) / PPB;
    if (gblocks < 256)
        zero_kernel<<<NBINS / 4 / 256 + 1, 256>>>();

    int nquads = (N + 3) / 4;
    hist_kernel<<<(nquads + 127) / 128, 128>>>(x, gidx, N);
    scan_kernel<<<NCHUNK, 1024>>>();
    scatter_kernel<<<(nquads + 127) / 128, 128>>>(x, gidx, N);

    fused_gather_kernel<<<gblocks, 512>>>(feat, (float2*)d_out, N, sc);
}

// round 16
// speedup vs baseline: 1.0461x; 1.0461x over previous
#include <cuda_runtime.h>
#include <math.h>
#include <stdint.h>

// HashGrid2D, Morton(512)+grid bucketed sort, fused gather (R14 gather):
//   hist(ILP4, saves rank) -> scan(int4/thread, atomic chunk base)
//   -> scatter(ILP4, atomic-free) -> fused gather: warp = level x 32 sorted
//      points, 256 pts/block, predicated XOR-pair ulonglong2 loads, packed
//      f32x2 lerp blend, conflict-free transpose (stride 257), __stcs
//      writeback, hist re-zero fused.

#define N_LEVELS 16
#define TBITS    19
#define TSIZE    (1u << TBITS)
#define HMASK    (TSIZE - 1u)
#define PRIME_Y  2654435761u

#define MAXN     1048576
#define KEYBITS  19
#define NBINS    (1 << KEYBITS)
#define NSCAN    (NBINS / 4096)     // 128 blocks, 4 bins/thread

#define PPB      256
#define GITER    8

struct ScaleArr { float s[N_LEVELS]; };

__device__ int    d_hist[NBINS];
__device__ int    d_counter;
__device__ int    d_rank[MAXN];
__device__ float4 d_pts[MAXN];

// -------- packed f32x2 helpers (sm_100+) --------
__device__ __forceinline__ unsigned long long f2_sub(unsigned long long a, unsigned long long b) {
    unsigned long long r;
    asm("sub.rn.f32x2 %0, %1, %2;" : "=l"(r) : "l"(a), "l"(b));
    return r;
}
__device__ __forceinline__ unsigned long long f2_fma(unsigned long long a, unsigned long long b, unsigned long long c) {
    unsigned long long r;
    asm("fma.rn.f32x2 %0, %1, %2, %3;" : "=l"(r) : "l"(a), "l"(b), "l"(c));
    return r;
}
__device__ __forceinline__ unsigned long long f2_bcast(float v) {
    unsigned long long r;
    asm("mov.b64 %0, {%1, %1};" : "=l"(r) : "f"(v));
    return r;
}

// -------- morton --------
__device__ __forceinline__ unsigned part1by1(unsigned v) {
    v &= 0xffffu;
    v = (v | (v << 8)) & 0x00FF00FFu;
    v = (v | (v << 4)) & 0x0F0F0F0Fu;
    v = (v | (v << 2)) & 0x33333333u;
    v = (v | (v << 1)) & 0x55555555u;
    return v;
}
__device__ __forceinline__ unsigned key19(float xf, float yf, int g) {
    unsigned mx = (unsigned)(xf * 512.0f); if (mx > 511u) mx = 511u;
    unsigned my = (unsigned)(yf * 512.0f); if (my > 511u) my = 511u;
    return (part1by1(mx) | (part1by1(my) << 1)) | ((unsigned)g << 18);
}

__global__ void zero_kernel() {
    int t = blockIdx.x * blockDim.x + threadIdx.x;
    if (t < NBINS / 4) ((int4*)d_hist)[t] = make_int4(0, 0, 0, 0);
    if (t == 0) d_counter = 0;
}

// -------- pass 1: histogram + rank capture --------
__global__ void __launch_bounds__(128) hist_kernel(
    const float2* __restrict__ x, const int* __restrict__ gidx, int N) {
    int t  = blockIdx.x * blockDim.x + threadIdx.x;
    int p0 = t * 4;
    if (p0 >= N) return;
    if (p0 + 3 < N) {
        const float4* x4 = (const float4*)x;
        float4 a = __ldg(&x4[t * 2]);
        float4 b = __ldg(&x4[t * 2 + 1]);
        int4   g = __ldg(&((const int4*)gidx)[t]);
        float xs[4] = {a.x, a.z, b.x, b.z};
        float ys[4] = {a.y, a.w, b.y, b.w};
        int   gs[4] = {g.x, g.y, g.z, g.w};
        int r[4];
        #pragma unroll
        for (int k = 0; k < 4; k++)
            r[k] = atomicAdd(&d_hist[key19(xs[k], ys[k], gs[k])], 1);
        ((int4*)(d_rank + p0))[0] = make_int4(r[0], r[1], r[2], r[3]);
    } else {
        for (int k = 0; k < 4 && p0 + k < N; k++) {
            float2 xy = __ldg(&x[p0 + k]);
            d_rank[p0 + k] =
                atomicAdd(&d_hist[key19(xy.x, xy.y, __ldg(&gidx[p0 + k]))], 1);
        }
    }
}

// -------- pass 2: scan, 4 bins per thread (int4), atomic chunk base --------
__global__ void __launch_bounds__(1024) scan_kernel() {
    __shared__ int warpsum[32];
    __shared__ int sbase;
    const int tid  = threadIdx.x;
    const int lane = tid & 31;
    const int wid  = tid >> 5;
    const int idx4 = blockIdx.x * 1024 + tid;    // int4 index

    const int4 v = ((const int4*)d_hist)[idx4];
    const int  s = v.x + v.y + v.z + v.w;

    int incl = s;
    #pragma unroll
    for (int d = 1; d < 32; d <<= 1) {
        int u = __shfl_up_sync(0xffffffffu, incl, d);
        if (lane >= d) incl += u;
    }
    if (lane == 31) warpsum[wid] = incl;
    __syncthreads();
    if (wid == 0) {
        int w = warpsum[lane];
        #pragma unroll
        for (int d = 1; d < 32; d <<= 1) {
            int u = __shfl_up_sync(0xffffffffu, w, d);
            if (lane >= d) w += u;
        }
        warpsum[lane] = w;
    }
    __syncthreads();
    const int inclT = incl + (wid ? warpsum[wid - 1] : 0);
    if (tid == 1023) sbase = atomicAdd(&d_counter, inclT);
    __syncthreads();

    const int e = sbase + inclT - s;     // global exclusive base, first bin
    int4 o;
    o.x = e;
    o.y = e + v.x;
    o.z = o.y + v.y;
    o.w = o.z + v.z;
    ((int4*)d_hist)[idx4] = o;
}

// -------- pass 3: atomic-free scatter --------
__global__ void __launch_bounds__(128) scatter_kernel(
    const float2* __restrict__ x, const int* __restrict__ gidx, int N) {
    int t  = blockIdx.x * blockDim.x + threadIdx.x;
    int p0 = t * 4;
    if (p0 >= N) return;
    if (p0 + 3 < N) {
        const float4* x4 = (const float4*)x;
        float4 xa = __ldg(&x4[t * 2]);
        float4 xb = __ldg(&x4[t * 2 + 1]);
        int4   g  = __ldg(&((const int4*)gidx)[t]);
        int4   r  = ((const int4*)(d_rank + p0))[0];
        float xs[4] = {xa.x, xa.z, xb.x, xb.z};
        float ys[4] = {xa.y, xa.w, xb.y, xb.w};
        int   gs[4] = {g.x, g.y, g.z, g.w};
        int   rs[4] = {r.x, r.y, r.z, r.w};
        int base[4];
        #pragma unroll
        for (int k = 0; k < 4; k++)
            base[k] = __ldg(&d_hist[key19(xs[k], ys[k], gs[k])]);
        #pragma unroll
        for (int k = 0; k < 4; k++)
            d_pts[base[k] + rs[k]] = make_float4(xs[k], ys[k],
                                                 __int_as_float(gs[k]),
                                                 __int_as_float(p0 + k));
    } else {
        for (int k = 0; k < 4 && p0 + k < N; k++) {
            float2 xy = __ldg(&x[p0 + k]);
            int    g  = __ldg(&gidx[p0 + k]);
            int pos = __ldg(&d_hist[key19(xy.x, xy.y, g)]) + d_rank[p0 + k];
            d_pts[pos] = make_float4(xy.x, xy.y,
                                     __int_as_float(g),
                                     __int_as_float(p0 + k));
        }
    }
}

// -------- pass 4: fused gather + writeback + hist re-zero (R14) --------
__global__ void __launch_bounds__(512) fused_gather_kernel(
    const float2* __restrict__ feat, float2* __restrict__ out2,
    int N, ScaleArr sc)
{
    __shared__ float4 spts[PPB];
    __shared__ float2 smres[N_LEVELS][PPB + 1];   // stride 257: conflict-free

    if (blockIdx.x < 256) {
        const int z = blockIdx.x * 512 + threadIdx.x;
        ((int4*)d_hist)[z] = make_int4(0, 0, 0, 0);
        if (z == 0) d_counter = 0;
    }

    const int i0   = blockIdx.x * PPB;
    const int warp = threadIdx.x >> 5;       // level
    const int lane = threadIdx.x & 31;

    #pragma unroll
    for (int k = 0; k < PPB / 512 + 1; k++) {
        const int j = threadIdx.x + k * 512;
        if (j < PPB) {
            const int i = i0 + j;
            spts[j] = (i < N) ? d_pts[i] : make_float4(0.f, 0.f, 0.f, 0.f);
        }
    }
    __syncthreads();

    const float s = sc.s[warp];
    const ulonglong2* __restrict__ warpbase =
        (const ulonglong2*)(feat + ((size_t)warp << TBITS));

    #pragma unroll
    for (int it = 0; it < GITER; it++) {
        const float4 pt = spts[it * 32 + lane];
        const unsigned gbit = __float_as_uint(pt.z);
        const float px = pt.x * s;
        const float py = pt.y * s;
        const int  ixi = __float2int_rd(px);
        const int  iyi = __float2int_rd(py);
        const float wx = px - (float)ixi;
        const float wy = py - (float)iyi;
        const unsigned ix = (unsigned)ixi;
        const unsigned iy = (unsigned)iyi;

        const ulonglong2* __restrict__ baseu =
            warpbase + ((size_t)(gbit & 1u) << 22);

        const unsigned hy0 = iy * PRIME_Y;
        const unsigned hy1 = hy0 + PRIME_Y;
        const unsigned h00 = ( ix       ^ hy0) & HMASK;
        const unsigned h10 = ((ix + 1u) ^ hy0) & HMASK;
        const unsigned h01 = ( ix       ^ hy1) & HMASK;
        const unsigned h11 = ((ix + 1u) ^ hy1) & HMASK;

        const ulonglong2 qa = __ldg(baseu + (h00 >> 1));
        const ulonglong2 qc = __ldg(baseu + (h01 >> 1));
        ulonglong2 qb = qa;
        ulonglong2 qd = qc;
        if (ix & 1u) {
            qb = __ldg(baseu + (h10 >> 1));
            qd = __ldg(baseu + (h11 >> 1));
        }

        const unsigned long long u00 = (h00 & 1u) ? qa.y : qa.x;
        const unsigned long long u10 = (h10 & 1u) ? qb.y : qb.x;
        const unsigned long long u01 = (h01 & 1u) ? qc.y : qc.x;
        const unsigned long long u11 = (h11 & 1u) ? qd.y : qd.x;

        const unsigned long long wx2 = f2_bcast(wx);
        const unsigned long long wy2 = f2_bcast(wy);
        const unsigned long long fx0 = f2_fma(wx2, f2_sub(u10, u00), u00);
        const unsigned long long fx1 = f2_fma(wx2, f2_sub(u11, u01), u01);
        const unsigned long long o   = f2_fma(wy2, f2_sub(fx1, fx0), fx0);

        float2 of;
        asm("mov.b64 {%0, %1}, %2;" : "=f"(of.x), "=f"(of.y) : "l"(o));
        smres[warp][it * 32 + lane] = of;
    }
    __syncthreads();

    #pragma unroll
    for (int r = 0; r < PPB * N_LEVELS / 512; r++) {
        const int idx = threadIdx.x + r * 512;
        const int p = idx >> 4;
        const int l = idx & 15;
        if (i0 + p < N) {
            const int p_orig = __float_as_int(spts[p].w);
            __stcs(&out2[(size_t)p_orig * N_LEVELS + l], smres[l][p]);
        }
    }
}

// -------- fallback (N > MAXN): flat paired kernel --------
__global__ void __launch_bounds__(256) hashgrid2d_paired_kernel(
    const float2* __restrict__ x, const float2* __restrict__ feat,
    const int* __restrict__ gidx, float2* __restrict__ out,
    int n_total, ScaleArr sc)
{
    int t = blockIdx.x * blockDim.x + threadIdx.x;
    if (t >= n_total) return;
    int level = t & 15, p = t >> 4;
    float2 xy = __ldg(&x[p]);
    int g = __ldg(&gidx[p]);
    float s = sc.s[level];
    float px = xy.x * s, py = xy.y * s;
    int ixi = __float2int_rd(px), iyi = __float2int_rd(py);
    float wx = px - (float)ixi, wy = py - (float)iyi;
    unsigned ix = (unsigned)ixi, iy = (unsigned)iyi;
    const float4* base4 = (const float4*)(feat + ((size_t)(g * N_LEVELS + level) << TBITS));
    unsigned hy0 = iy * PRIME_Y, hy1 = hy0 + PRIME_Y;
    unsigned h00 = (ix ^ hy0) & HMASK, h01 = (ix ^ hy1) & HMASK;
    unsigned h10 = ((ix + 1u) ^ hy0) & HMASK;
    unsigned h11 = ((ix + 1u) ^ hy1) & HMASK;
    float4 qa = __ldg(base4 + (h00 >> 1));
    float4 qc = __ldg(base4 + (h01 >> 1));
    float4 qb = qa, qd = qc;
    if (ix & 1u) {
        qb = __ldg(base4 + (h10 >> 1));
        qd = __ldg(base4 + (h11 >> 1));
    }
    float2 f00 = (h00 & 1u) ? make_float2(qa.z, qa.w) : make_float2(qa.x, qa.y);
    float2 f10 = (h10 & 1u) ? make_float2(qb.z, qb.w) : make_float2(qb.x, qb.y);
    float2 f01 = (h01 & 1u) ? make_float2(qc.z, qc.w) : make_float2(qc.x, qc.y);
    float2 f11 = (h11 & 1u) ? make_float2(qd.z, qd.w) : make_float2(qd.x, qd.y);
    float w00 = (1.0f - wx) * (1.0f - wy), w10 = wx * (1.0f - wy);
    float w01 = (1.0f - wx) * wy,          w11 = wx * wy;
    float2 o;
    o.x = w00 * f00.x + w10 * f10.x + w01 * f01.x + w11 * f11.x;
    o.y = w00 * f00.y + w10 * f10.y + w01 * f01.y + w11 * f11.y;
    out[t] = o;
}

extern "C" void kernel_launch(void* const* d_in, const int* in_sizes, int n_in,
                              void* d_out, int out_size)
{
    const float2* x    = (const float2*)d_in[0];
    const float2* feat = (const float2*)d_in[1];
    const int*    gidx = (const int*)d_in[2];

    int N = in_sizes[0] / 2;

    ScaleArr sc;
    double bw = exp((log(512.0) - log(16.0)) / (double)(N_LEVELS - 1));
    for (int i = 0; i < N_LEVELS; i++) {
        int res = (int)(16.0 * pow(bw, (double)i));
        sc.s[i] = (float)(res - 1);
    }

    if (N > MAXN) {
        int n_total = N * N_LEVELS;
        hashgrid2d_paired_kernel<<<(n_total + 255) / 256, 256>>>(
            x, feat, gidx, (float2*)d_out, n_total, sc);
        return;
    }

    int gblocks = (N + PPB - 1) / PPB;
    if (gblocks < 256)
        zero_kernel<<<NBINS / 4 / 256 + 1, 256>>>();

    int nquads = (N + 3) / 4;
    hist_kernel<<<(nquads + 127) / 128, 128>>>(x, gidx, N);
    scan_kernel<<<NSCAN, 1024>>>();
    scatter_kernel<<<(nquads + 127) / 128, 128>>>(x, gidx, N);

    fused_gather_kernel<<<gblocks, 512>>>(feat, (float2*)d_out, N, sc);
}

// round 17
// speedup vs baseline: 1.0626x; 1.0157x over previous
#include <cuda_runtime.h>
#include <math.h>
#include <stdint.h>

// HashGrid2D, Morton(512)+grid bucketed sort, fused gather (R16 base + PDL):
//   hist(ILP4, saves rank) -> [PDL] scan(int4/thread) -> [PDL] scatter(ILP4,
//   atomic-free, keys computed BEFORE griddepsync) -> [PDL] fused gather
//   (warp = level x 32 sorted points, 256 pts/block, predicated XOR-pair
//   ulonglong2 loads, f32x2 lerp, conflict-free transpose, __stcs, hist
//   re-zero fused after griddepsync).

#define N_LEVELS 16
#define TBITS    19
#define TSIZE    (1u << TBITS)
#define HMASK    (TSIZE - 1u)
#define PRIME_Y  2654435761u

#define MAXN     1048576
#define KEYBITS  19
#define NBINS    (1 << KEYBITS)
#define NSCAN    (NBINS / 4096)     // 128 blocks, 4 bins/thread

#define PPB      256
#define GITER    8

struct ScaleArr { float s[N_LEVELS]; };

__device__ int    d_hist[NBINS];
__device__ int    d_counter;
__device__ int    d_rank[MAXN];
__device__ float4 d_pts[MAXN];

// -------- packed f32x2 helpers (sm_100+) --------
__device__ __forceinline__ unsigned long long f2_sub(unsigned long long a, unsigned long long b) {
    unsigned long long r;
    asm("sub.rn.f32x2 %0, %1, %2;" : "=l"(r) : "l"(a), "l"(b));
    return r;
}
__device__ __forceinline__ unsigned long long f2_fma(unsigned long long a, unsigned long long b, unsigned long long c) {
    unsigned long long r;
    asm("fma.rn.f32x2 %0, %1, %2, %3;" : "=l"(r) : "l"(a), "l"(b), "l"(c));
    return r;
}
__device__ __forceinline__ unsigned long long f2_bcast(float v) {
    unsigned long long r;
    asm("mov.b64 %0, {%1, %1};" : "=l"(r) : "f"(v));
    return r;
}

// -------- morton --------
__device__ __forceinline__ unsigned part1by1(unsigned v) {
    v &= 0xffffu;
    v = (v | (v << 8)) & 0x00FF00FFu;
    v = (v | (v << 4)) & 0x0F0F0F0Fu;
    v = (v | (v << 2)) & 0x33333333u;
    v = (v | (v << 1)) & 0x55555555u;
    return v;
}
__device__ __forceinline__ unsigned key19(float xf, float yf, int g) {
    unsigned mx = (unsigned)(xf * 512.0f); if (mx > 511u) mx = 511u;
    unsigned my = (unsigned)(yf * 512.0f); if (my > 511u) my = 511u;
    return (part1by1(mx) | (part1by1(my) << 1)) | ((unsigned)g << 18);
}

__global__ void zero_kernel() {
    int t = blockIdx.x * blockDim.x + threadIdx.x;
    if (t < NBINS / 4) ((int4*)d_hist)[t] = make_int4(0, 0, 0, 0);
    if (t == 0) d_counter = 0;
}

// -------- pass 1: histogram + rank capture --------
__global__ void __launch_bounds__(128) hist_kernel(
    const float2* __restrict__ x, const int* __restrict__ gidx, int N) {
    int t  = blockIdx.x * blockDim.x + threadIdx.x;
    int p0 = t * 4;
    if (p0 >= N) return;
    if (p0 + 3 < N) {
        const float4* x4 = (const float4*)x;
        float4 a = __ldg(&x4[t * 2]);
        float4 b = __ldg(&x4[t * 2 + 1]);
        int4   g = __ldg(&((const int4*)gidx)[t]);
        float xs[4] = {a.x, a.z, b.x, b.z};
        float ys[4] = {a.y, a.w, b.y, b.w};
        int   gs[4] = {g.x, g.y, g.z, g.w};
        int r[4];
        #pragma unroll
        for (int k = 0; k < 4; k++)
            r[k] = atomicAdd(&d_hist[key19(xs[k], ys[k], gs[k])], 1);
        ((int4*)(d_rank + p0))[0] = make_int4(r[0], r[1], r[2], r[3]);
    } else {
        for (int k = 0; k < 4 && p0 + k < N; k++) {
            float2 xy = __ldg(&x[p0 + k]);
            d_rank[p0 + k] =
                atomicAdd(&d_hist[key19(xy.x, xy.y, __ldg(&gidx[p0 + k]))], 1);
        }
    }
}

// -------- pass 2: scan, 4 bins/thread (int4), atomic chunk base, PDL --------
__global__ void __launch_bounds__(1024) scan_kernel() {
    cudaGridDependencySynchronize();   // wait for hist

    __shared__ int warpsum[32];
    __shared__ int sbase;
    const int tid  = threadIdx.x;
    const int lane = tid & 31;
    const int wid  = tid >> 5;
    const int idx4 = blockIdx.x * 1024 + tid;

    const int4 v = ((const int4*)d_hist)[idx4];
    const int  s = v.x + v.y + v.z + v.w;

    int incl = s;
    #pragma unroll
    for (int d = 1; d < 32; d <<= 1) {
        int u = __shfl_up_sync(0xffffffffu, incl, d);
        if (lane >= d) incl += u;
    }
    if (lane == 31) warpsum[wid] = incl;
    __syncthreads();
    if (wid == 0) {
        int w = warpsum[lane];
        #pragma unroll
        for (int d = 1; d < 32; d <<= 1) {
            int u = __shfl_up_sync(0xffffffffu, w, d);
            if (lane >= d) w += u;
        }
        warpsum[lane] = w;
    }
    __syncthreads();
    const int inclT = incl + (wid ? warpsum[wid - 1] : 0);
    if (tid == 1023) sbase = atomicAdd(&d_counter, inclT);
    __syncthreads();

    const int e = sbase + inclT - s;
    int4 o;
    o.x = e;
    o.y = e + v.x;
    o.z = o.y + v.y;
    o.w = o.z + v.z;
    ((int4*)d_hist)[idx4] = o;
}

// -------- pass 3: atomic-free scatter, PDL (keys before sync) --------
__global__ void __launch_bounds__(128) scatter_kernel(
    const float2* __restrict__ x, const int* __restrict__ gidx, int N) {
    int t  = blockIdx.x * blockDim.x + threadIdx.x;
    int p0 = t * 4;

    if (p0 + 3 < N) {
        // preamble: external inputs + key computation, independent of scan
        const float4* x4 = (const float4*)x;
        float4 xa = __ldg(&x4[t * 2]);
        float4 xb = __ldg(&x4[t * 2 + 1]);
        int4   g  = __ldg(&((const int4*)gidx)[t]);
        float xs[4] = {xa.x, xa.z, xb.x, xb.z};
        float ys[4] = {xa.y, xa.w, xb.y, xb.w};
        int   gs[4] = {g.x, g.y, g.z, g.w};
        unsigned keys[4];
        #pragma unroll
        for (int k = 0; k < 4; k++)
            keys[k] = key19(xs[k], ys[k], gs[k]);

        cudaGridDependencySynchronize();   // wait for scan (transitively hist)

        int4 r = ((const int4*)(d_rank + p0))[0];
        int  rs[4] = {r.x, r.y, r.z, r.w};
        int base[4];
        #pragma unroll
        for (int k = 0; k < 4; k++)
            base[k] = __ldg(&d_hist[keys[k]]);
        #pragma unroll
        for (int k = 0; k < 4; k++)
            d_pts[base[k] + rs[k]] = make_float4(xs[k], ys[k],
                                                 __int_as_float(gs[k]),
                                                 __int_as_float(p0 + k));
    } else {
        cudaGridDependencySynchronize();
        for (int k = 0; k < 4 && p0 + k < N; k++) {
            float2 xy = __ldg(&x[p0 + k]);
            int    g  = __ldg(&gidx[p0 + k]);
            int pos = __ldg(&d_hist[key19(xy.x, xy.y, g)]) + d_rank[p0 + k];
            d_pts[pos] = make_float4(xy.x, xy.y,
                                     __int_as_float(g),
                                     __int_as_float(p0 + k));
        }
    }
}

// -------- pass 4: fused gather + writeback + hist re-zero, PDL --------
__global__ void __launch_bounds__(512) fused_gather_kernel(
    const float2* __restrict__ feat, float2* __restrict__ out2,
    int N, ScaleArr sc)
{
    cudaGridDependencySynchronize();   // scatter done (also guards hist re-zero)

    __shared__ float4 spts[PPB];
    __shared__ float2 smres[N_LEVELS][PPB + 1];

    if (blockIdx.x < 256) {
        const int z = blockIdx.x * 512 + threadIdx.x;
        ((int4*)d_hist)[z] = make_int4(0, 0, 0, 0);
        if (z == 0) d_counter = 0;
    }

    const int i0   = blockIdx.x * PPB;
    const int warp = threadIdx.x >> 5;
    const int lane = threadIdx.x & 31;

    #pragma unroll
    for (int k = 0; k < PPB / 512 + 1; k++) {
        const int j = threadIdx.x + k * 512;
        if (j < PPB) {
            const int i = i0 + j;
            spts[j] = (i < N) ? d_pts[i] : make_float4(0.f, 0.f, 0.f, 0.f);
        }
    }
    __syncthreads();

    const float s = sc.s[warp];
    const ulonglong2* __restrict__ warpbase =
        (const ulonglong2*)(feat + ((size_t)warp << TBITS));

    #pragma unroll
    for (int it = 0; it < GITER; it++) {
        const float4 pt = spts[it * 32 + lane];
        const unsigned gbit = __float_as_uint(pt.z);
        const float px = pt.x * s;
        const float py = pt.y * s;
        const int  ixi = __float2int_rd(px);
        const int  iyi = __float2int_rd(py);
        const float wx = px - (float)ixi;
        const float wy = py - (float)iyi;
        const unsigned ix = (unsigned)ixi;
        const unsigned iy = (unsigned)iyi;

        const ulonglong2* __restrict__ baseu =
            warpbase + ((size_t)(gbit & 1u) << 22);

        const unsigned hy0 = iy * PRIME_Y;
        const unsigned hy1 = hy0 + PRIME_Y;
        const unsigned h00 = ( ix       ^ hy0) & HMASK;
        const unsigned h10 = ((ix + 1u) ^ hy0) & HMASK;
        const unsigned h01 = ( ix       ^ hy1) & HMASK;
        const unsigned h11 = ((ix + 1u) ^ hy1) & HMASK;

        const ulonglong2 qa = __ldg(baseu + (h00 >> 1));
        const ulonglong2 qc = __ldg(baseu + (h01 >> 1));
        ulonglong2 qb = qa;
        ulonglong2 qd = qc;
        if (ix & 1u) {
            qb = __ldg(baseu + (h10 >> 1));
            qd = __ldg(baseu + (h11 >> 1));
        }

        const unsigned long long u00 = (h00 & 1u) ? qa.y : qa.x;
        const unsigned long long u10 = (h10 & 1u) ? qb.y : qb.x;
        const unsigned long long u01 = (h01 & 1u) ? qc.y : qc.x;
        const unsigned long long u11 = (h11 & 1u) ? qd.y : qd.x;

        const unsigned long long wx2 = f2_bcast(wx);
        const unsigned long long wy2 = f2_bcast(wy);
        const unsigned long long fx0 = f2_fma(wx2, f2_sub(u10, u00), u00);
        const unsigned long long fx1 = f2_fma(wx2, f2_sub(u11, u01), u01);
        const unsigned long long o   = f2_fma(wy2, f2_sub(fx1, fx0), fx0);

        float2 of;
        asm("mov.b64 {%0, %1}, %2;" : "=f"(of.x), "=f"(of.y) : "l"(o));
        smres[warp][it * 32 + lane] = of;
    }
    __syncthreads();

    #pragma unroll
    for (int r = 0; r < PPB * N_LEVELS / 512; r++) {
        const int idx = threadIdx.x + r * 512;
        const int p = idx >> 4;
        const int l = idx & 15;
        if (i0 + p < N) {
            const int p_orig = __float_as_int(spts[p].w);
            __stcs(&out2[(size_t)p_orig * N_LEVELS + l], smres[l][p]);
        }
    }
}

// -------- fallback (N > MAXN): flat paired kernel --------
__global__ void __launch_bounds__(256) hashgrid2d_paired_kernel(
    const float2* __restrict__ x, const float2* __restrict__ feat,
    const int* __restrict__ gidx, float2* __restrict__ out,
    int n_total, ScaleArr sc)
{
    int t = blockIdx.x * blockDim.x + threadIdx.x;
    if (t >= n_total) return;
    int level = t & 15, p = t >> 4;
    float2 xy = __ldg(&x[p]);
    int g = __ldg(&gidx[p]);
    float s = sc.s[level];
    float px = xy.x * s, py = xy.y * s;
    int ixi = __float2int_rd(px), iyi = __float2int_rd(py);
    float wx = px - (float)ixi, wy = py - (float)iyi;
    unsigned ix = (unsigned)ixi, iy = (unsigned)iyi;
    const float4* base4 = (const float4*)(feat + ((size_t)(g * N_LEVELS + level) << TBITS));
    unsigned hy0 = iy * PRIME_Y, hy1 = hy0 + PRIME_Y;
    unsigned h00 = (ix ^ hy0) & HMASK, h01 = (ix ^ hy1) & HMASK;
    unsigned h10 = ((ix + 1u) ^ hy0) & HMASK;
    unsigned h11 = ((ix + 1u) ^ hy1) & HMASK;
    float4 qa = __ldg(base4 + (h00 >> 1));
    float4 qc = __ldg(base4 + (h01 >> 1));
    float4 qb = qa, qd = qc;
    if (ix & 1u) {
        qb = __ldg(base4 + (h10 >> 1));
        qd = __ldg(base4 + (h11 >> 1));
    }
    float2 f00 = (h00 & 1u) ? make_float2(qa.z, qa.w) : make_float2(qa.x, qa.y);
    float2 f10 = (h10 & 1u) ? make_float2(qb.z, qb.w) : make_float2(qb.x, qb.y);
    float2 f01 = (h01 & 1u) ? make_float2(qc.z, qc.w) : make_float2(qc.x, qc.y);
    float2 f11 = (h11 & 1u) ? make_float2(qd.z, qd.w) : make_float2(qd.x, qd.y);
    float w00 = (1.0f - wx) * (1.0f - wy), w10 = wx * (1.0f - wy);
    float w01 = (1.0f - wx) * wy,          w11 = wx * wy;
    float2 o;
    o.x = w00 * f00.x + w10 * f10.x + w01 * f01.x + w11 * f11.x;
    o.y = w00 * f00.y + w10 * f10.y + w01 * f01.y + w11 * f11.y;
    out[t] = o;
}

// -------- host: PDL launch helper --------
static inline void launch_pdl(void* func, dim3 grid, dim3 block,
                              void** args) {
    cudaLaunchConfig_t cfg = {};
    cfg.gridDim  = grid;
    cfg.blockDim = block;
    cudaLaunchAttribute attr[1];
    attr[0].id = cudaLaunchAttributeProgrammaticStreamSerialization;
    attr[0].val.programmaticStreamSerializationAllowed = 1;
    cfg.attrs = attr;
    cfg.numAttrs = 1;
    cudaLaunchKernelExC(&cfg, func, args);
}

extern "C" void kernel_launch(void* const* d_in, const int* in_sizes, int n_in,
                              void* d_out, int out_size)
{
    const float2* x    = (const float2*)d_in[0];
    const float2* feat = (const float2*)d_in[1];
    const int*    gidx = (const int*)d_in[2];

    int N = in_sizes[0] / 2;

    ScaleArr sc;
    double bw = exp((log(512.0) - log(16.0)) / (double)(N_LEVELS - 1));
    for (int i = 0; i < N_LEVELS; i++) {
        int res = (int)(16.0 * pow(bw, (double)i));
        sc.s[i] = (float)(res - 1);
    }

    if (N > MAXN) {
        int n_total = N * N_LEVELS;
        hashgrid2d_paired_kernel<<<(n_total + 255) / 256, 256>>>(
            x, feat, gidx, (float2*)d_out, n_total, sc);
        return;
    }

    int gblocks = (N + PPB - 1) / PPB;
    if (gblocks < 256)
        zero_kernel<<<NBINS / 4 / 256 + 1, 256>>>();

    int nquads = (N + 3) / 4;
    int pblocks = (nquads + 127) / 128;

    // hist: plain launch (must not overlap previous replay's gather hist-zero)
    hist_kernel<<<pblocks, 128>>>(x, gidx, N);

    // scan: PDL
    {
        void* args[] = {};
        launch_pdl((void*)scan_kernel, dim3(NSCAN), dim3(1024), args);
    }
    // scatter: PDL, keys computed before griddepsync
    {
        const float2* xa = x; const int* ga = gidx; int Na = N;
        void* args[] = {(void*)&xa, (void*)&ga, (void*)&Na};
        launch_pdl((void*)scatter_kernel, dim3(pblocks), dim3(128), args);
    }
    // gather: PDL
    {
        const float2* fa = feat; float2* oa = (float2*)d_out; int Na = N;
        ScaleArr sca = sc;
        void* args[] = {(void*)&fa, (void*)&oa, (void*)&Na, (void*)&sca};
        launch_pdl((void*)fused_gather_kernel, dim3(gblocks), dim3(512), args);
    }
}